// round 3
// baseline (speedup 1.0000x reference)
#include <cuda_runtime.h>

// SpectralConv2D reduced form:
//   up[b,n]    = mean_c inputs[b,n,c]                       (B=64, N=1024)
//   base[f,p]  = omega[f,i,j] * (lambda_in[i]-lambda_out[j]), p=i*3+j
//   out[b,l,f] = relu( sum_p base[f,p] * (enc[n]-dec[l]) * up[b,n] ),
//                n = (l/30)*32 + (l%30) + (p/3)*32 + (p%3)
// Output layout: (B, 30, 30, F) row-major, F contiguous.

#define B_   64
#define W_   32
#define C_   8
#define F_   64
#define O2_  30
#define L_   900
#define N_   1024

// scratch (allocation-free rule: __device__ globals)
__device__ float g_up[B_ * N_];          // channel means
__device__ float g_base[9 * F_];         // base transposed: [p][f]

// ---------------- Kernel 1: channel-mean + base assembly ----------------
__global__ __launch_bounds__(256)
void prep_kernel(const float* __restrict__ inputs,
                 const float* __restrict__ omega_diag,
                 const float* __restrict__ omega_triu,
                 const float* __restrict__ omega_tril,
                 const float* __restrict__ lambda_in,
                 const float* __restrict__ lambda_out)
{
    int pid = blockIdx.x * 256 + threadIdx.x;     // 0 .. 65535
    const float4* p = (const float4*)(inputs + (size_t)pid * C_);
    float4 v0 = p[0];
    float4 v1 = p[1];
    g_up[pid] = (v0.x + v0.y + v0.z + v0.w + v1.x + v1.y + v1.z + v1.w) * 0.125f;

    if (blockIdx.x == 0) {
        // 576 base entries, 256 threads -> strided loop (R2 bug: single pass
        // only covered f<29, zeroing filters 29..63)
        for (int idx = threadIdx.x; idx < F_ * 9; idx += 256) {
            int f = idx / 9;
            int pp = idx - f * 9;
            int i = pp / 3, j = pp - i * 3;
            float w;
            if (i == j) {
                w = omega_diag[f * 3 + i];
            } else if (i < j) {
                int t = (i == 0) ? (j - 1) : 2;       // (0,1)->0 (0,2)->1 (1,2)->2
                w = omega_triu[f * 3 + t];
            } else {
                int t = (i == 1) ? 0 : (1 + j);       // (1,0)->0 (2,0)->1 (2,1)->2
                w = omega_tril[f * 3 + t];
            }
            g_base[pp * F_ + f] = w * (lambda_in[i] - lambda_out[j]);
        }
    }
}

// ---------------- Kernel 2: main compute, 1 thread = 1 float4 of out ----------------
// grid (57, 64): blockIdx.y = b, x covers L*16 = 14400 thread-slots.
__global__ __launch_bounds__(256)
void conv_kernel(const float* __restrict__ use_encode,   // (N)
                 const float* __restrict__ use_decode,   // (L)
                 float* __restrict__ out)                // (B, L, F)
{
    int slot = blockIdx.x * 256 + threadIdx.x;   // 0 .. 14591
    int l  = slot >> 4;                          // output position
    int f4 = slot & 15;                          // which float4 of 64 filters
    if (l >= L_) return;
    int b = blockIdx.y;

    int r = l / O2_;
    int c = l - r * O2_;
    int start = r * W_ + c;
    float dec = __ldg(&use_decode[l]);

    const float* upb = g_up + b * N_;
    float y[9];
    #pragma unroll
    for (int pp = 0; pp < 9; pp++) {
        int n = start + (pp / 3) * W_ + (pp % 3);
        y[pp] = (__ldg(&use_encode[n]) - dec) * __ldg(&upb[n]);
    }

    float4 acc = make_float4(0.f, 0.f, 0.f, 0.f);
    #pragma unroll
    for (int pp = 0; pp < 9; pp++) {
        float4 w = *(const float4*)(g_base + pp * F_ + f4 * 4);
        acc.x = fmaf(w.x, y[pp], acc.x);
        acc.y = fmaf(w.y, y[pp], acc.y);
        acc.z = fmaf(w.z, y[pp], acc.z);
        acc.w = fmaf(w.w, y[pp], acc.w);
    }
    acc.x = fmaxf(acc.x, 0.f);
    acc.y = fmaxf(acc.y, 0.f);
    acc.z = fmaxf(acc.z, 0.f);
    acc.w = fmaxf(acc.w, 0.f);

    ((float4*)(out + ((size_t)b * L_ + l) * F_))[f4] = acc;
}

extern "C" void kernel_launch(void* const* d_in, const int* in_sizes, int n_in,
                              void* d_out, int out_size) {
    (void)in_sizes; (void)n_in; (void)out_size;
    const float* inputs      = (const float*)d_in[0];
    const float* omega_diag  = (const float*)d_in[1];
    const float* omega_triu  = (const float*)d_in[2];
    const float* omega_tril  = (const float*)d_in[3];
    const float* lambda_in   = (const float*)d_in[4];
    const float* lambda_out  = (const float*)d_in[5];
    const float* use_encode  = (const float*)d_in[6];
    const float* use_decode  = (const float*)d_in[7];
    float* out = (float*)d_out;

    prep_kernel<<<256, 256>>>(inputs, omega_diag, omega_triu, omega_tril,
                              lambda_in, lambda_out);

    dim3 grid2((L_ * 16 + 255) / 256, B_);   // (57, 64)
    conv_kernel<<<grid2, 256>>>(use_encode, use_decode, out);
}

// round 4
// speedup vs baseline: 1.2460x; 1.2460x over previous
#include <cuda_runtime.h>

// SpectralConv2D, fully fused single kernel.
//   up[b,n]    = mean_c inputs[b,n,c]                       (B=64, N=1024)
//   base[f,p]  = omega[f,i,j] * (lambda_in[i]-lambda_out[j]), p=i*3+j
//   out[b,l,f] = relu( sum_p base[f,p] * (enc[n]-dec[l]) * up[b,n] ),
//                n = (l/30)*32 + (l%30) + (p/3)*32 + (p%3)
// Block = (batch b, tile of 60 positions = 2 output rows = 4 input rows).

#define B_    64
#define W_    32
#define C_    8
#define F_    64
#define O2_   30
#define L_    900
#define N_    1024
#define TILE  60          // 15 tiles * 60 = 900, exact

__global__ __launch_bounds__(256)
void spectral_fused_kernel(
    const float* __restrict__ inputs,      // (B, 32, 32, 8)
    const float* __restrict__ omega_diag,  // (F, 3)
    const float* __restrict__ omega_triu,  // (1, F*3)
    const float* __restrict__ omega_tril,  // (1, F*3)
    const float* __restrict__ lambda_in,   // (3, 1)
    const float* __restrict__ lambda_out,  // (1, 3)
    const float* __restrict__ use_encode,  // (N)
    const float* __restrict__ use_decode,  // (L)
    float* __restrict__ out)               // (B, 30, 30, F)
{
    __shared__ float up_s[128];            // 4 input rows x 32 cols, channel means
    __shared__ float eu_s[128];            // enc[n] * up[n]
    __shared__ float dec_s[TILE];
    __shared__ float base_s[9 * F_];       // [p][f]
    __shared__ float y_s[TILE * 10];       // [pos][p], padded stride 10

    const int tid = threadIdx.x;
    const int kt  = blockIdx.x;            // 0..14 (position tile)
    const int b   = blockIdx.y;
    const int r0  = kt * 2;                // first output/input row of tile
    const int l0  = kt * TILE;

    // ---------------- Phase A ----------------
    if (tid < 128) {
        // one pixel per thread: input rows r0..r0+3, all 32 cols
        int row = tid >> 5, col = tid & 31;
        int n = (r0 + row) * W_ + col;
        const float4* p = (const float4*)(inputs + ((size_t)b * N_ + n) * C_);
        float4 v0 = p[0];
        float4 v1 = p[1];
        float m = (v0.x + v0.y + v0.z + v0.w + v1.x + v1.y + v1.z + v1.w) * 0.125f;
        up_s[tid] = m;
        eu_s[tid] = m * __ldg(&use_encode[n]);
    } else {
        int t = tid - 128;                 // 0..127
        if (t < TILE)
            dec_s[t] = __ldg(&use_decode[l0 + t]);
        // base assembly: 576 entries over 128 threads (tiny cached reads)
        for (int idx = t; idx < F_ * 9; idx += 128) {
            int f  = idx / 9;
            int pp = idx - f * 9;
            int i = pp / 3, j = pp - i * 3;
            float w;
            if (i == j) {
                w = __ldg(&omega_diag[f * 3 + i]);
            } else if (i < j) {
                int tt = (i == 0) ? (j - 1) : 2;   // (0,1)->0 (0,2)->1 (1,2)->2
                w = __ldg(&omega_triu[f * 3 + tt]);
            } else {
                int tt = (i == 1) ? 0 : (1 + j);   // (1,0)->0 (2,0)->1 (2,1)->2
                w = __ldg(&omega_tril[f * 3 + tt]);
            }
            base_s[pp * F_ + f] = w * (__ldg(&lambda_in[i]) - __ldg(&lambda_out[j]));
        }
    }
    __syncthreads();

    // ---------------- Phase B: y[pos][p] computed once ----------------
    for (int e = tid; e < TILE * 9; e += 256) {
        int pos = e / 9;
        int pp  = e - pos * 9;
        int orow = pos / O2_;              // 0 or 1
        int ocol = pos - orow * O2_;
        int idx = (orow + pp / 3) * W_ + ocol + (pp % 3);
        y_s[pos * 10 + pp] = eu_s[idx] - dec_s[pos] * up_s[idx];
    }
    __syncthreads();

    // ---------------- Phase C: out tile ----------------
    const int f4    = tid & 15;            // which float4 of 64 filters
    const int group = tid >> 4;            // 0..15

    float4 w[9];
    #pragma unroll
    for (int pp = 0; pp < 9; pp++)
        w[pp] = *(const float4*)(base_s + pp * F_ + f4 * 4);

    float* obase = out + ((size_t)b * L_ + l0) * F_;

    #pragma unroll
    for (int k2 = 0; k2 < 4; k2++) {
        int pos = group + k2 * 16;
        if (pos < TILE) {
            float y[9];
            #pragma unroll
            for (int pp = 0; pp < 9; pp++)
                y[pp] = y_s[pos * 10 + pp];

            float4 acc = make_float4(0.f, 0.f, 0.f, 0.f);
            #pragma unroll
            for (int pp = 0; pp < 9; pp++) {
                acc.x = fmaf(w[pp].x, y[pp], acc.x);
                acc.y = fmaf(w[pp].y, y[pp], acc.y);
                acc.z = fmaf(w[pp].z, y[pp], acc.z);
                acc.w = fmaf(w[pp].w, y[pp], acc.w);
            }
            acc.x = fmaxf(acc.x, 0.f);
            acc.y = fmaxf(acc.y, 0.f);
            acc.z = fmaxf(acc.z, 0.f);
            acc.w = fmaxf(acc.w, 0.f);

            ((float4*)(obase + pos * F_))[f4] = acc;
        }
    }
}

extern "C" void kernel_launch(void* const* d_in, const int* in_sizes, int n_in,
                              void* d_out, int out_size) {
    (void)in_sizes; (void)n_in; (void)out_size;
    const float* inputs      = (const float*)d_in[0];
    const float* omega_diag  = (const float*)d_in[1];
    const float* omega_triu  = (const float*)d_in[2];
    const float* omega_tril  = (const float*)d_in[3];
    const float* lambda_in   = (const float*)d_in[4];
    const float* lambda_out  = (const float*)d_in[5];
    const float* use_encode  = (const float*)d_in[6];
    const float* use_decode  = (const float*)d_in[7];
    float* out = (float*)d_out;

    dim3 grid(L_ / TILE, B_);   // (15, 64) = 960 blocks
    spectral_fused_kernel<<<grid, 256>>>(
        inputs, omega_diag, omega_triu, omega_tril,
        lambda_in, lambda_out, use_encode, use_decode, out);
}

// round 5
// speedup vs baseline: 1.4060x; 1.1284x over previous
#include <cuda_runtime.h>

// SpectralConv2D, fused single kernel (R5: branchless base, vectorized y, no div/mod).
//   up[b,n]    = mean_c inputs[b,n,c]
//   base[f,p]  = omega[f,i,j] * (lambda_in[i]-lambda_out[j]), p=i*3+j
//   out[b,l,f] = relu( sum_p base[f,p] * (enc[n]-dec[l]) * up[b,n] )
// Block = (batch b, tile of 60 positions = 2 output rows = 4 input rows).

#define B_    64
#define W_    32
#define C_    8
#define F_    64
#define O2_   30
#define L_    900
#define N_    1024
#define TILE  60

// per-tap LUTs: p=i*3+j; src: 0=diag,1=triu,2=tril; t: index within that src row
__constant__ int c_sel[9] = {0,1,1,2,0,1,2,2,0};
__constant__ int c_t  [9] = {0,0,1,0,1,2,1,2,2};
__constant__ int c_i  [9] = {0,0,0,1,1,1,2,2,2};
__constant__ int c_j  [9] = {0,1,2,0,1,2,0,1,2};

__global__ __launch_bounds__(256, 4)
void spectral_fused_kernel(
    const float* __restrict__ inputs,      // (B, 32, 32, 8)
    const float* __restrict__ omega_diag,  // (F, 3)
    const float* __restrict__ omega_triu,  // (F*3)
    const float* __restrict__ omega_tril,  // (F*3)
    const float* __restrict__ lambda_in,   // (3)
    const float* __restrict__ lambda_out,  // (3)
    const float* __restrict__ use_encode,  // (N)
    const float* __restrict__ use_decode,  // (L)
    float* __restrict__ out)               // (B, L, F)
{
    __shared__ float up_s[128];            // 4 input rows x 32 cols
    __shared__ float eu_s[128];            // enc*up
    __shared__ float dec_s[TILE];
    __shared__ float base_s[9 * F_];       // [p][f]
    __shared__ float y_s[TILE * 12];       // [pos][12], 16B-aligned rows

    const int tid = threadIdx.x;
    const int kt  = blockIdx.x;            // 0..14
    const int b   = blockIdx.y;
    const int r0  = kt * 2;
    const int l0  = kt * TILE;

    // ---------------- Phase A ----------------
    if (tid < 128) {
        int n = (r0 + (tid >> 5)) * W_ + (tid & 31);
        const float4* p = (const float4*)(inputs + ((size_t)b * N_ + n) * C_);
        float4 v0 = p[0];
        float4 v1 = p[1];
        float m = (v0.x + v0.y + v0.z + v0.w + v1.x + v1.y + v1.z + v1.w) * 0.125f;
        up_s[tid] = m;
        eu_s[tid] = m * __ldg(&use_encode[n]);
    } else if (tid < 128 + TILE) {
        dec_s[tid - 128] = __ldg(&use_decode[l0 + tid - 128]);
    }

    // branchless base assembly: idx -> pp = idx>>6, f = idx&63  (576 entries)
    {
        const float* srcs[3] = { omega_diag, omega_triu, omega_tril };
        #pragma unroll
        for (int k = 0; k < 3; k++) {
            int idx = tid + k * 256;
            if (k < 2 || tid < 64) {       // k=0,1 always valid; k=2 only tid<64
                int pp = idx >> 6;
                int f  = idx & 63;
                float w = __ldg(&srcs[c_sel[pp]][f * 3 + c_t[pp]]);
                float lam = __ldg(&lambda_in[c_i[pp]]) - __ldg(&lambda_out[c_j[pp]]);
                base_s[idx] = w * lam;
            }
        }
    }
    __syncthreads();

    // ---------------- Phase B: one thread per position ----------------
    if (tid < TILE) {
        int orow = (tid >= 30) ? 1 : 0;
        int idx0 = orow * 2 + tid;         // orow*32 + (tid - orow*30)
        float dec = dec_s[tid];
        float4 ya, yb, yc;
        ya.x = eu_s[idx0 +  0] - dec * up_s[idx0 +  0];
        ya.y = eu_s[idx0 +  1] - dec * up_s[idx0 +  1];
        ya.z = eu_s[idx0 +  2] - dec * up_s[idx0 +  2];
        ya.w = eu_s[idx0 + 32] - dec * up_s[idx0 + 32];
        yb.x = eu_s[idx0 + 33] - dec * up_s[idx0 + 33];
        yb.y = eu_s[idx0 + 34] - dec * up_s[idx0 + 34];
        yb.z = eu_s[idx0 + 64] - dec * up_s[idx0 + 64];
        yb.w = eu_s[idx0 + 65] - dec * up_s[idx0 + 65];
        yc.x = eu_s[idx0 + 66] - dec * up_s[idx0 + 66];
        yc.y = 0.f; yc.z = 0.f; yc.w = 0.f;
        float4* yrow = (float4*)(y_s + tid * 12);
        yrow[0] = ya; yrow[1] = yb; yrow[2] = yc;
    }

    // all threads: prefetch weights (base_s stable since sync1)
    const int f4 = tid & 15;
    const int g  = tid >> 4;               // 0..15; g==15 idle in Phase C
    float4 w[9];
    #pragma unroll
    for (int pp = 0; pp < 9; pp++)
        w[pp] = *(const float4*)(base_s + pp * F_ + f4 * 4);

    __syncthreads();

    // ---------------- Phase C ----------------
    if (g < 15) {
        float* obase = out + ((size_t)b * L_ + l0) * F_;
        #pragma unroll
        for (int k2 = 0; k2 < 4; k2++) {
            int pos = g * 4 + k2;          // 0..59 exactly
            const float4* yrow = (const float4*)(y_s + pos * 12);
            float4 ya = yrow[0];
            float4 yb = yrow[1];
            float4 yc = yrow[2];
            float y[9] = { ya.x, ya.y, ya.z, ya.w, yb.x, yb.y, yb.z, yb.w, yc.x };

            float4 acc = make_float4(0.f, 0.f, 0.f, 0.f);
            #pragma unroll
            for (int pp = 0; pp < 9; pp++) {
                acc.x = fmaf(w[pp].x, y[pp], acc.x);
                acc.y = fmaf(w[pp].y, y[pp], acc.y);
                acc.z = fmaf(w[pp].z, y[pp], acc.z);
                acc.w = fmaf(w[pp].w, y[pp], acc.w);
            }
            acc.x = fmaxf(acc.x, 0.f);
            acc.y = fmaxf(acc.y, 0.f);
            acc.z = fmaxf(acc.z, 0.f);
            acc.w = fmaxf(acc.w, 0.f);

            ((float4*)(obase + pos * F_))[f4] = acc;
        }
    }
}

extern "C" void kernel_launch(void* const* d_in, const int* in_sizes, int n_in,
                              void* d_out, int out_size) {
    (void)in_sizes; (void)n_in; (void)out_size;
    const float* inputs      = (const float*)d_in[0];
    const float* omega_diag  = (const float*)d_in[1];
    const float* omega_triu  = (const float*)d_in[2];
    const float* omega_tril  = (const float*)d_in[3];
    const float* lambda_in   = (const float*)d_in[4];
    const float* lambda_out  = (const float*)d_in[5];
    const float* use_encode  = (const float*)d_in[6];
    const float* use_decode  = (const float*)d_in[7];
    float* out = (float*)d_out;

    dim3 grid(L_ / TILE, B_);   // (15, 64) = 960 blocks
    spectral_fused_kernel<<<grid, 256>>>(
        inputs, omega_diag, omega_triu, omega_tril,
        lambda_in, lambda_out, use_encode, use_decode, out);
}